// round 9
// baseline (speedup 1.0000x reference)
#include <cuda_runtime.h>
#include <cstdint>
#include <math.h>

// Problem shape (fixed)
constexpr int B_ = 4, T_ = 2048, C_ = 1024, H_ = 16, D_ = 64;
constexpr int M_ = B_ * T_;  // 8192

// Scratch (allocations are forbidden; use __device__ globals)
__device__ float g_q[M_ * C_];
__device__ float g_k[M_ * C_];
__device__ float g_v[M_ * C_];
__device__ float g_y[M_ * C_];
__device__ float g_x[M_ * C_];        // tf32-rounded x
__device__ float g_w[4 * C_ * C_];    // tf32-rounded wq|wk|wv|wp

// ---------------------------------------------------------------------------
// helpers
// ---------------------------------------------------------------------------
__device__ __forceinline__ uint32_t smem_u32(const void* p) {
    uint32_t a;
    asm("{ .reg .u64 t; cvta.to.shared.u64 t, %1; cvt.u32.u64 %0, t; }"
        : "=r"(a) : "l"(p));
    return a;
}
__device__ __forceinline__ uint32_t tf32r(float x) {
    uint32_t u;
    asm("cvt.rna.tf32.f32 %0, %1;" : "=r"(u) : "f"(x));
    return u;
}
__device__ __forceinline__ void mma_u(float* c, uint32_t a0, uint32_t a1,
                                      uint32_t a2, uint32_t a3,
                                      uint32_t b0, uint32_t b1) {
    asm volatile(
        "mma.sync.aligned.m16n8k8.row.col.f32.tf32.tf32.f32 "
        "{%0,%1,%2,%3}, {%4,%5,%6,%7}, {%8,%9}, {%0,%1,%2,%3};"
        : "+f"(c[0]), "+f"(c[1]), "+f"(c[2]), "+f"(c[3])
        : "r"(a0), "r"(a1), "r"(a2), "r"(a3), "r"(b0), "r"(b1));
}
#define CP_ASYNC16(dst, src) \
    asm volatile("cp.async.cg.shared.global [%0], [%1], 16;" \
                 :: "r"(dst), "l"(src) : "memory")
#define CP_COMMIT() asm volatile("cp.async.commit_group;" ::: "memory")
#define CP_WAIT0()  asm volatile("cp.async.wait_group 0;" ::: "memory")

// ---------------------------------------------------------------------------
// Pre-round x and the four weight matrices to tf32 (RNA) in gmem.
// ---------------------------------------------------------------------------
__global__ __launch_bounds__(256) void round_tf32(
    const float* __restrict__ x,
    const float* __restrict__ wq, const float* __restrict__ wk,
    const float* __restrict__ wv, const float* __restrict__ wp,
    float* __restrict__ gx, float* __restrict__ gw)
{
    const int XF = M_ * C_ / 4;
    const int WF = C_ * C_ / 4;
    int i4 = blockIdx.x * 256 + threadIdx.x;
    const float4* src;
    float4* dst;
    if (i4 < XF) {
        src = reinterpret_cast<const float4*>(x);
        dst = reinterpret_cast<float4*>(gx);
    } else {
        int j = i4 - XF;
        int w = j / WF;
        i4 = j - w * WF;
        const float* ws = (w == 0) ? wq : (w == 1) ? wk : (w == 2) ? wv : wp;
        src = reinterpret_cast<const float4*>(ws);
        dst = reinterpret_cast<float4*>(gw + (size_t)w * C_ * C_);
    }
    float4 t = src[i4];
    uint4 u;
    u.x = tf32r(t.x); u.y = tf32r(t.y); u.z = tf32r(t.z); u.w = tf32r(t.w);
    *reinterpret_cast<uint4*>(&dst[i4]) = u;
}

// ---------------------------------------------------------------------------
// GEMM via mma.sync tf32: out = A*W^T + bias.  A,W pre-rounded to tf32.
// CTA tile 256x128, BK=32, cp.async double-buffer, one barrier per chunk.
// 256 threads = 8 warps (4M x 2N), warp tile 64x64.
// SMEM stride 40 (==8 mod 32): conflict-free LDS.64 fragment loads.
// blockIdx.z selects (W, bias, out) so QKV runs as one launch.
// ---------------------------------------------------------------------------
constexpr int BK = 32, LDSG = 40;
constexpr int A_STF = 256 * LDSG;                 // A floats per stage (10240)
constexpr int B_STF = 128 * LDSG;                 // B floats per stage (5120)
constexpr int GEMM_SMEM = (2 * A_STF + 2 * B_STF) * 4;  // 122880 B

__global__ __launch_bounds__(256, 1) void gemm_mma(
    const float* __restrict__ A, const float* __restrict__ Wb,
    const float* __restrict__ bias0, const float* __restrict__ bias1,
    const float* __restrict__ bias2,
    float* __restrict__ out0, float* __restrict__ out1,
    float* __restrict__ out2)
{
    extern __shared__ __align__(16) float smg[];
    const uint32_t sbase = smem_u32(smg);
    const int tid = threadIdx.x;
    const int lane = tid & 31, wid = tid >> 5;
    const int warp_m = wid & 3, warp_n = wid >> 2;        // 4 x 2
    const int row0 = blockIdx.y * 256, col0 = blockIdx.x * 128;
    const int r = lane >> 2, kc = lane & 3;
    const int z = blockIdx.z;

    const float* W = Wb + (size_t)z * C_ * C_;
    const float* bias = (z == 0) ? bias0 : (z == 1) ? bias1 : bias2;
    float* out = (z == 0) ? out0 : (z == 1) ? out1 : out2;

    float acc[4][8][4];
#pragma unroll
    for (int i = 0; i < 4; i++)
#pragma unroll
        for (int j = 0; j < 8; j++)
#pragma unroll
            for (int q = 0; q < 4; q++) acc[i][j][q] = 0.f;

    const int lrow = tid >> 3, lc4 = (tid & 7) * 4;       // 32 rows x 8 col4
    const float* gA = &A[(size_t)(row0 + lrow) * C_ + lc4];
    const float* gW = &W[(size_t)(col0 + lrow) * C_ + lc4];
    const uint32_t soff = (uint32_t)(lrow * LDSG + lc4) * 4;

    auto issue = [&](int c) {
        const int k0 = c * BK;
        const uint32_t sa = sbase + (uint32_t)((c & 1) * A_STF) * 4 + soff;
        const uint32_t sb = sbase + (uint32_t)(2 * A_STF + (c & 1) * B_STF) * 4 + soff;
#pragma unroll
        for (int it = 0; it < 8; it++)
            CP_ASYNC16(sa + (uint32_t)(it * 32 * LDSG) * 4,
                       gA + (size_t)it * 32 * C_ + k0);
#pragma unroll
        for (int it = 0; it < 4; it++)
            CP_ASYNC16(sb + (uint32_t)(it * 32 * LDSG) * 4,
                       gW + (size_t)it * 32 * C_ + k0);
        CP_COMMIT();
    };

    issue(0);

    const int NCH = C_ / BK;  // 32
    for (int c = 0; c < NCH; c++) {
        CP_WAIT0();
        __syncthreads();
        if (c + 1 < NCH) issue(c + 1);

        const float* as = smg + (c & 1) * A_STF;
        const float* bs = smg + 2 * A_STF + (c & 1) * B_STF;
        const int ar = warp_m * 64 + r;
        const int br = warp_n * 64 + r;

#pragma unroll
        for (int kk = 0; kk < 4; kk++) {
            const int ko = 8 * kk + 2 * kc;
            uint2 a01[4], a23[4];
#pragma unroll
            for (int mt = 0; mt < 4; mt++) {
                a01[mt] = *reinterpret_cast<const uint2*>(
                    &as[(ar + mt * 16) * LDSG + ko]);
                a23[mt] = *reinterpret_cast<const uint2*>(
                    &as[(ar + mt * 16 + 8) * LDSG + ko]);
            }
#pragma unroll
            for (int nt = 0; nt < 8; nt++) {
                uint2 bb = *reinterpret_cast<const uint2*>(
                    &bs[(br + nt * 8) * LDSG + ko]);
#pragma unroll
                for (int mt = 0; mt < 4; mt++)
                    mma_u(acc[mt][nt], a01[mt].x, a23[mt].x,
                          a01[mt].y, a23[mt].y, bb.x, bb.y);
            }
        }
    }

    // Epilogue: bias + direct float2 stores
    const int orow = row0 + warp_m * 64 + r;
    const int ocol = col0 + warp_n * 64 + 2 * kc;
#pragma unroll
    for (int nt = 0; nt < 8; nt++) {
        const int cg = ocol + nt * 8;
        const float b0 = bias[cg], b1 = bias[cg + 1];
#pragma unroll
        for (int mt = 0; mt < 4; mt++) {
            float2 v0 = make_float2(acc[mt][nt][0] + b0, acc[mt][nt][1] + b1);
            float2 v1 = make_float2(acc[mt][nt][2] + b0, acc[mt][nt][3] + b1);
            *reinterpret_cast<float2*>(&out[(size_t)(orow + mt * 16) * C_ + cg]) = v0;
            *reinterpret_cast<float2*>(&out[(size_t)(orow + mt * 16 + 8) * C_ + cg]) = v1;
        }
    }
}

// ---------------------------------------------------------------------------
// RoPE in place on q and k (fp32).
// ---------------------------------------------------------------------------
__global__ __launch_bounds__(256) void rope_kernel(float* __restrict__ q,
                                                   float* __restrict__ k)
{
    int idx = blockIdx.x * 256 + threadIdx.x;
    int half = idx & 31;
    int h = (idx >> 5) & 15;
    int t = (idx >> 9) & 2047;
    int b = idx >> 20;

    float alpha = exp2f(-(float)half * 0.41524101186092029f);
    float ang = (float)t * alpha;
    float c = cosf(ang), s = sinf(ang);

    size_t off = ((size_t)b * T_ + t) * C_ + h * D_ + half;
    float xr = q[off], xi = q[off + 32];
    q[off] = xr * c - xi * s;
    q[off + 32] = xr * s + xi * c;
    xr = k[off]; xi = k[off + 32];
    k[off] = xr * c - xi * s;
    k[off + 32] = xr * s + xi * c;
}

// ---------------------------------------------------------------------------
// Tensor-core flash attention (causal, tf32 mma, online softmax).
// Unchanged from R8 (y stored tf32-rounded for the proj GEMM).
// ---------------------------------------------------------------------------
constexpr int ALD2 = 72;
constexpr int ATTN_SMEM2 = (128 + 64 + 64) * ALD2 * 4;  // 73728 B

__global__ __launch_bounds__(256, 2) void attn_mma(
    const float* __restrict__ q, const float* __restrict__ k,
    const float* __restrict__ v, float* __restrict__ y)
{
    extern __shared__ __align__(16) uint32_t sma[];
    uint32_t* Qs = sma;                    // [128][72]
    uint32_t* Ks = sma + 128 * ALD2;       // [64][72]
    uint32_t* Vt = sma + 192 * ALD2;       // [64][72] (V transposed: [d][s])

    const int tid = threadIdx.x;
    const int lane = tid & 31, w = tid >> 5;
    const int r = lane >> 2, kc = lane & 3;
    const int qb = blockIdx.x, bh = blockIdx.y;
    const int b = bh >> 4, h = bh & 15;
    const int q0 = qb * 128;
    const size_t base = ((size_t)b * T_) * C_ + h * D_;

    // Load Q tile (scaled by 1/8, tf32)
#pragma unroll
    for (int it = 0; it < 8; it++) {
        int f = tid + it * 256;
        int row = f >> 4, d4 = f & 15;
        float4 t = *reinterpret_cast<const float4*>(
            &q[base + (size_t)(q0 + row) * C_ + d4 * 4]);
        uint4 u;
        u.x = tf32r(t.x * 0.125f); u.y = tf32r(t.y * 0.125f);
        u.z = tf32r(t.z * 0.125f); u.w = tf32r(t.w * 0.125f);
        *reinterpret_cast<uint4*>(&Qs[row * ALD2 + d4 * 4]) = u;
    }

    float sc[8][4];
    float yacc[4][2][4];
#pragma unroll
    for (int mt = 0; mt < 4; mt++)
#pragma unroll
        for (int nt = 0; nt < 2; nt++)
#pragma unroll
            for (int j = 0; j < 4; j++) yacc[mt][nt][j] = 0.f;
    float mA = -1e30f, mB = -1e30f, lA = 0.f, lB = 0.f;

    const int nit = 2 * qb + 2;
    for (int itk = 0; itk < nit; itk++) {
        const int s0 = itk * 64;
        __syncthreads();
#pragma unroll
        for (int i = 0; i < 4; i++) {
            int f = tid + i * 256;
            int row = f >> 4, d4 = f & 15;
            float4 t = *reinterpret_cast<const float4*>(
                &k[base + (size_t)(s0 + row) * C_ + d4 * 4]);
            uint4 u;
            u.x = tf32r(t.x); u.y = tf32r(t.y);
            u.z = tf32r(t.z); u.w = tf32r(t.w);
            *reinterpret_cast<uint4*>(&Ks[row * ALD2 + d4 * 4]) = u;
        }
#pragma unroll
        for (int i = 0; i < 4; i++) {
            int f = tid + i * 256;
            int d = f & 63, sb = (f >> 6) * 4;
            const float* vp = &v[base + (size_t)(s0 + sb) * C_ + d];
            uint4 u;
            u.x = tf32r(vp[0]);
            u.y = tf32r(vp[C_]);
            u.z = tf32r(vp[2 * C_]);
            u.w = tf32r(vp[3 * C_]);
            *reinterpret_cast<uint4*>(&Vt[d * ALD2 + sb]) = u;
        }
        __syncthreads();

        const int qrow0 = q0 + 16 * w;
        if (s0 > qrow0 + 15) continue;

        // ---- S = Q K^T ----
#pragma unroll
        for (int nt = 0; nt < 8; nt++)
#pragma unroll
            for (int j = 0; j < 4; j++) sc[nt][j] = 0.f;

#pragma unroll
        for (int kk = 0; kk < 8; kk++) {
            uint2 a01 = *reinterpret_cast<const uint2*>(
                &Qs[(16 * w + r) * ALD2 + 8 * kk + 2 * kc]);
            uint2 a23 = *reinterpret_cast<const uint2*>(
                &Qs[(16 * w + r + 8) * ALD2 + 8 * kk + 2 * kc]);
#pragma unroll
            for (int nt = 0; nt < 8; nt++) {
                uint2 bb = *reinterpret_cast<const uint2*>(
                    &Ks[(8 * nt + r) * ALD2 + 8 * kk + 2 * kc]);
                mma_u(sc[nt], a01.x, a23.x, a01.y, a23.y, bb.x, bb.y);
            }
        }

        // ---- causal mask ----
        if (s0 + 63 > qrow0) {
            const int qA = qrow0 + r, qB = qA + 8;
#pragma unroll
            for (int nt = 0; nt < 8; nt++) {
                int sg = s0 + 8 * nt + 2 * kc;
                if (sg > qA)     sc[nt][0] = -1e30f;
                if (sg + 1 > qA) sc[nt][1] = -1e30f;
                if (sg > qB)     sc[nt][2] = -1e30f;
                if (sg + 1 > qB) sc[nt][3] = -1e30f;
            }
        }

        // ---- online softmax ----
        float mxA = -1e30f, mxB = -1e30f;
#pragma unroll
        for (int nt = 0; nt < 8; nt++) {
            mxA = fmaxf(mxA, fmaxf(sc[nt][0], sc[nt][1]));
            mxB = fmaxf(mxB, fmaxf(sc[nt][2], sc[nt][3]));
        }
        mxA = fmaxf(mxA, __shfl_xor_sync(0xffffffffu, mxA, 1));
        mxA = fmaxf(mxA, __shfl_xor_sync(0xffffffffu, mxA, 2));
        mxB = fmaxf(mxB, __shfl_xor_sync(0xffffffffu, mxB, 1));
        mxB = fmaxf(mxB, __shfl_xor_sync(0xffffffffu, mxB, 2));
        float mnA = fmaxf(mA, mxA), mnB = fmaxf(mB, mxB);
        float cA = __expf(mA - mnA), cB = __expf(mB - mnB);
        mA = mnA; mB = mnB;
        float psA = 0.f, psB = 0.f;
#pragma unroll
        for (int nt = 0; nt < 8; nt++) {
            float p0 = __expf(sc[nt][0] - mnA);
            float p1 = __expf(sc[nt][1] - mnA);
            float p2 = __expf(sc[nt][2] - mnB);
            float p3 = __expf(sc[nt][3] - mnB);
            psA += p0 + p1; psB += p2 + p3;
            sc[nt][0] = p0; sc[nt][1] = p1; sc[nt][2] = p2; sc[nt][3] = p3;
        }
        psA += __shfl_xor_sync(0xffffffffu, psA, 1);
        psA += __shfl_xor_sync(0xffffffffu, psA, 2);
        psB += __shfl_xor_sync(0xffffffffu, psB, 1);
        psB += __shfl_xor_sync(0xffffffffu, psB, 2);
        lA = lA * cA + psA;
        lB = lB * cB + psB;

        float cc0 = __shfl_sync(0xffffffffu, cA, 8 * kc);
        float cc1 = __shfl_sync(0xffffffffu, cA, 8 * kc + 4);
        float cc2 = __shfl_sync(0xffffffffu, cB, 8 * kc);
        float cc3 = __shfl_sync(0xffffffffu, cB, 8 * kc + 4);
#pragma unroll
        for (int mt = 0; mt < 4; mt++) {
            yacc[mt][0][0] *= cc0; yacc[mt][0][1] *= cc1;
            yacc[mt][0][2] *= cc0; yacc[mt][0][3] *= cc1;
            yacc[mt][1][0] *= cc2; yacc[mt][1][1] *= cc3;
            yacc[mt][1][2] *= cc2; yacc[mt][1][3] *= cc3;
        }

        // ---- P to tf32 ----
#pragma unroll
        for (int nt = 0; nt < 8; nt++)
#pragma unroll
            for (int j = 0; j < 4; j++)
                sc[nt][j] = __uint_as_float(tf32r(sc[nt][j]));

        // ---- yT += Vt * P^T ----
#pragma unroll
        for (int kk = 0; kk < 8; kk++) {
            uint32_t pb0 = __float_as_uint(sc[kk][0]);
            uint32_t pb1 = __float_as_uint(sc[kk][1]);
            uint32_t pb2 = __float_as_uint(sc[kk][2]);
            uint32_t pb3 = __float_as_uint(sc[kk][3]);
#pragma unroll
            for (int mt = 0; mt < 4; mt++) {
                uint2 v01 = *reinterpret_cast<const uint2*>(
                    &Vt[(16 * mt + r) * ALD2 + 8 * kk + 2 * kc]);
                uint2 v23 = *reinterpret_cast<const uint2*>(
                    &Vt[(16 * mt + r + 8) * ALD2 + 8 * kk + 2 * kc]);
                mma_u(yacc[mt][0], v01.x, v23.x, v01.y, v23.y, pb0, pb1);
                mma_u(yacc[mt][1], v01.x, v23.x, v01.y, v23.y, pb2, pb3);
            }
        }
    }

    // ---- epilogue ----
    float iA = 1.f / lA, iB = 1.f / lB;
    float i0 = __shfl_sync(0xffffffffu, iA, 8 * kc);
    float i1 = __shfl_sync(0xffffffffu, iA, 8 * kc + 4);
    float i2 = __shfl_sync(0xffffffffu, iB, 8 * kc);
    float i3 = __shfl_sync(0xffffffffu, iB, 8 * kc + 4);

    __syncthreads();
    float* stg = reinterpret_cast<float*>(Qs);
#pragma unroll
    for (int mt = 0; mt < 4; mt++) {
        const int dr = 16 * mt + r;
#pragma unroll
        for (int nt = 0; nt < 2; nt++) {
            const int qc = 16 * w + 8 * nt + 2 * kc;
            float f0 = (nt ? i2 : i0), f1 = (nt ? i3 : i1);
            stg[qc * ALD2 + dr]           = yacc[mt][nt][0] * f0;
            stg[(qc + 1) * ALD2 + dr]     = yacc[mt][nt][1] * f1;
            stg[qc * ALD2 + dr + 8]       = yacc[mt][nt][2] * f0;
            stg[(qc + 1) * ALD2 + dr + 8] = yacc[mt][nt][3] * f1;
        }
    }
    __syncthreads();
#pragma unroll
    for (int it = 0; it < 8; it++) {
        int f = tid + it * 256;
        int row = f >> 4, d4 = f & 15;
        float4 o = *reinterpret_cast<const float4*>(&stg[row * ALD2 + d4 * 4]);
        uint4 u;
        u.x = tf32r(o.x); u.y = tf32r(o.y); u.z = tf32r(o.z); u.w = tf32r(o.w);
        *reinterpret_cast<uint4*>(
            &y[base + (size_t)(q0 + row) * C_ + d4 * 4]) = u;
    }
}

// ---------------------------------------------------------------------------
// Launch
// ---------------------------------------------------------------------------
extern "C" void kernel_launch(void* const* d_in, const int* in_sizes, int n_in,
                              void* d_out, int out_size)
{
    const float* x  = (const float*)d_in[0];
    const float* wq = (const float*)d_in[1];
    const float* bq = (const float*)d_in[2];
    const float* wk = (const float*)d_in[3];
    const float* bk = (const float*)d_in[4];
    const float* wv = (const float*)d_in[5];
    const float* bv = (const float*)d_in[6];
    const float* wp = (const float*)d_in[7];
    const float* bp = (const float*)d_in[8];
    float* out = (float*)d_out;

    float *qp, *kp, *vp, *yp, *xp, *wr;
    cudaGetSymbolAddress((void**)&qp, g_q);
    cudaGetSymbolAddress((void**)&kp, g_k);
    cudaGetSymbolAddress((void**)&vp, g_v);
    cudaGetSymbolAddress((void**)&yp, g_y);
    cudaGetSymbolAddress((void**)&xp, g_x);
    cudaGetSymbolAddress((void**)&wr, g_w);

    cudaFuncSetAttribute(gemm_mma,
                         cudaFuncAttributeMaxDynamicSharedMemorySize, GEMM_SMEM);
    cudaFuncSetAttribute(attn_mma,
                         cudaFuncAttributeMaxDynamicSharedMemorySize, ATTN_SMEM2);

    // Pre-round x and weights to tf32 (RNA) once.
    const int RBLK = (M_ * C_ / 4 + 4 * C_ * C_ / 4) / 256;  // 12288
    round_tf32<<<RBLK, 256>>>(x, wq, wk, wv, wp, xp, wr);

    // Fused QKV projection: blockIdx.z selects weight/bias/output.
    dim3 qkv_grid(C_ / 128, M_ / 256, 3);   // (8, 32, 3)
    gemm_mma<<<qkv_grid, 256, GEMM_SMEM>>>(xp, wr, bq, bk, bv, qp, kp, vp);

    rope_kernel<<<(B_ * T_ * H_ * 32) / 256, 256>>>(qp, kp);

    dim3 agrid(16, 64);                     // q-tiles x (b*h)
    attn_mma<<<agrid, 256, ATTN_SMEM2>>>(qp, kp, vp, yp);

    // Output projection (z = 0 only).
    dim3 proj_grid(C_ / 128, M_ / 256, 1);  // (8, 32, 1)
    gemm_mma<<<proj_grid, 256, GEMM_SMEM>>>(yp, wr + 3 * (size_t)C_ * C_,
                                            bp, bp, bp, out, out, out);
}

// round 14
// speedup vs baseline: 1.0677x; 1.0677x over previous
#include <cuda_runtime.h>
#include <cstdint>
#include <math.h>

// Problem shape (fixed)
constexpr int B_ = 4, T_ = 2048, C_ = 1024, H_ = 16, D_ = 64;
constexpr int M_ = B_ * T_;  // 8192

// Scratch (allocations are forbidden; use __device__ globals)
__device__ float g_q[M_ * C_];
__device__ float g_k[M_ * C_];
__device__ float g_v[M_ * C_];
__device__ float g_y[M_ * C_];
__device__ float g_x[M_ * C_];        // tf32-rounded x
__device__ float g_w[4 * C_ * C_];    // tf32-rounded wq|wk|wv|wp

// ---------------------------------------------------------------------------
// helpers
// ---------------------------------------------------------------------------
__device__ __forceinline__ uint32_t smem_u32(const void* p) {
    uint32_t a;
    asm("{ .reg .u64 t; cvta.to.shared.u64 t, %1; cvt.u32.u64 %0, t; }"
        : "=r"(a) : "l"(p));
    return a;
}
__device__ __forceinline__ uint32_t tf32r(float x) {
    uint32_t u;
    asm("cvt.rna.tf32.f32 %0, %1;" : "=r"(u) : "f"(x));
    return u;
}
__device__ __forceinline__ void mma_u(float* c, uint32_t a0, uint32_t a1,
                                      uint32_t a2, uint32_t a3,
                                      uint32_t b0, uint32_t b1) {
    asm volatile(
        "mma.sync.aligned.m16n8k8.row.col.f32.tf32.tf32.f32 "
        "{%0,%1,%2,%3}, {%4,%5,%6,%7}, {%8,%9}, {%0,%1,%2,%3};"
        : "+f"(c[0]), "+f"(c[1]), "+f"(c[2]), "+f"(c[3])
        : "r"(a0), "r"(a1), "r"(a2), "r"(a3), "r"(b0), "r"(b1));
}
#define CP_ASYNC16(dst, src) \
    asm volatile("cp.async.cg.shared.global [%0], [%1], 16;" \
                 :: "r"(dst), "l"(src) : "memory")
#define CP_COMMIT() asm volatile("cp.async.commit_group;" ::: "memory")
#define CP_WAIT0()  asm volatile("cp.async.wait_group 0;" ::: "memory")

// ---------------------------------------------------------------------------
// Pre-round x and the four weight matrices to tf32 (RNA) in gmem.
// ---------------------------------------------------------------------------
__global__ __launch_bounds__(256) void round_tf32(
    const float* __restrict__ x,
    const float* __restrict__ wq, const float* __restrict__ wk,
    const float* __restrict__ wv, const float* __restrict__ wp,
    float* __restrict__ gx, float* __restrict__ gw)
{
    const int XF = M_ * C_ / 4;
    const int WF = C_ * C_ / 4;
    int i4 = blockIdx.x * 256 + threadIdx.x;
    const float4* src;
    float4* dst;
    if (i4 < XF) {
        src = reinterpret_cast<const float4*>(x);
        dst = reinterpret_cast<float4*>(gx);
    } else {
        int j = i4 - XF;
        int w = j / WF;
        i4 = j - w * WF;
        const float* ws = (w == 0) ? wq : (w == 1) ? wk : (w == 2) ? wv : wp;
        src = reinterpret_cast<const float4*>(ws);
        dst = reinterpret_cast<float4*>(gw + (size_t)w * C_ * C_);
    }
    float4 t = src[i4];
    uint4 u;
    u.x = tf32r(t.x); u.y = tf32r(t.y); u.z = tf32r(t.z); u.w = tf32r(t.w);
    *reinterpret_cast<uint4*>(&dst[i4]) = u;
}

// ---------------------------------------------------------------------------
// GEMM via mma.sync tf32 (as R9): CTA 256x128, BK=32, cp.async 2-stage.
// blockIdx.z selects (W, bias, out). Outputs with z == round_z are stored
// tf32-rounded (v path feeds raw cp.async in attention).
// ---------------------------------------------------------------------------
constexpr int BK = 32, LDSG = 40;
constexpr int A_STF = 256 * LDSG;
constexpr int B_STF = 128 * LDSG;
constexpr int GEMM_SMEM = (2 * A_STF + 2 * B_STF) * 4;  // 122880 B

__global__ __launch_bounds__(256, 1) void gemm_mma(
    const float* __restrict__ A, const float* __restrict__ Wb,
    const float* __restrict__ bias0, const float* __restrict__ bias1,
    const float* __restrict__ bias2,
    float* __restrict__ out0, float* __restrict__ out1,
    float* __restrict__ out2, int round_z)
{
    extern __shared__ __align__(16) float smg[];
    const uint32_t sbase = smem_u32(smg);
    const int tid = threadIdx.x;
    const int lane = tid & 31, wid = tid >> 5;
    const int warp_m = wid & 3, warp_n = wid >> 2;        // 4 x 2
    const int row0 = blockIdx.y * 256, col0 = blockIdx.x * 128;
    const int r = lane >> 2, kc = lane & 3;
    const int z = blockIdx.z;

    const float* W = Wb + (size_t)z * C_ * C_;
    const float* bias = (z == 0) ? bias0 : (z == 1) ? bias1 : bias2;
    float* out = (z == 0) ? out0 : (z == 1) ? out1 : out2;
    const bool rnd = (z == round_z);

    float acc[4][8][4];
#pragma unroll
    for (int i = 0; i < 4; i++)
#pragma unroll
        for (int j = 0; j < 8; j++)
#pragma unroll
            for (int q = 0; q < 4; q++) acc[i][j][q] = 0.f;

    const int lrow = tid >> 3, lc4 = (tid & 7) * 4;
    const float* gA = &A[(size_t)(row0 + lrow) * C_ + lc4];
    const float* gW = &W[(size_t)(col0 + lrow) * C_ + lc4];
    const uint32_t soff = (uint32_t)(lrow * LDSG + lc4) * 4;

    auto issue = [&](int c) {
        const int k0 = c * BK;
        const uint32_t sa = sbase + (uint32_t)((c & 1) * A_STF) * 4 + soff;
        const uint32_t sb = sbase + (uint32_t)(2 * A_STF + (c & 1) * B_STF) * 4 + soff;
#pragma unroll
        for (int it = 0; it < 8; it++)
            CP_ASYNC16(sa + (uint32_t)(it * 32 * LDSG) * 4,
                       gA + (size_t)it * 32 * C_ + k0);
#pragma unroll
        for (int it = 0; it < 4; it++)
            CP_ASYNC16(sb + (uint32_t)(it * 32 * LDSG) * 4,
                       gW + (size_t)it * 32 * C_ + k0);
        CP_COMMIT();
    };

    issue(0);

    const int NCH = C_ / BK;  // 32
    for (int c = 0; c < NCH; c++) {
        CP_WAIT0();
        __syncthreads();
        if (c + 1 < NCH) issue(c + 1);

        const float* as = smg + (c & 1) * A_STF;
        const float* bs = smg + 2 * A_STF + (c & 1) * B_STF;
        const int ar = warp_m * 64 + r;
        const int br = warp_n * 64 + r;

#pragma unroll
        for (int kk = 0; kk < 4; kk++) {
            const int ko = 8 * kk + 2 * kc;
            uint2 a01[4], a23[4];
#pragma unroll
            for (int mt = 0; mt < 4; mt++) {
                a01[mt] = *reinterpret_cast<const uint2*>(
                    &as[(ar + mt * 16) * LDSG + ko]);
                a23[mt] = *reinterpret_cast<const uint2*>(
                    &as[(ar + mt * 16 + 8) * LDSG + ko]);
            }
#pragma unroll
            for (int nt = 0; nt < 8; nt++) {
                uint2 bb = *reinterpret_cast<const uint2*>(
                    &bs[(br + nt * 8) * LDSG + ko]);
#pragma unroll
                for (int mt = 0; mt < 4; mt++)
                    mma_u(acc[mt][nt], a01[mt].x, a23[mt].x,
                          a01[mt].y, a23[mt].y, bb.x, bb.y);
            }
        }
    }

    const int orow = row0 + warp_m * 64 + r;
    const int ocol = col0 + warp_n * 64 + 2 * kc;
#pragma unroll
    for (int nt = 0; nt < 8; nt++) {
        const int cg = ocol + nt * 8;
        const float b0 = bias[cg], b1 = bias[cg + 1];
#pragma unroll
        for (int mt = 0; mt < 4; mt++) {
            float2 v0 = make_float2(acc[mt][nt][0] + b0, acc[mt][nt][1] + b1);
            float2 v1 = make_float2(acc[mt][nt][2] + b0, acc[mt][nt][3] + b1);
            if (rnd) {
                v0.x = __uint_as_float(tf32r(v0.x));
                v0.y = __uint_as_float(tf32r(v0.y));
                v1.x = __uint_as_float(tf32r(v1.x));
                v1.y = __uint_as_float(tf32r(v1.y));
            }
            *reinterpret_cast<float2*>(&out[(size_t)(orow + mt * 16) * C_ + cg]) = v0;
            *reinterpret_cast<float2*>(&out[(size_t)(orow + mt * 16 + 8) * C_ + cg]) = v1;
        }
    }
}

// ---------------------------------------------------------------------------
// RoPE in place on q and k; stores tf32-rounded (attention consumes raw).
// ---------------------------------------------------------------------------
__global__ __launch_bounds__(256) void rope_kernel(float* __restrict__ q,
                                                   float* __restrict__ k)
{
    int idx = blockIdx.x * 256 + threadIdx.x;
    int half = idx & 31;
    int h = (idx >> 5) & 15;
    int t = (idx >> 9) & 2047;
    int b = idx >> 20;

    float alpha = exp2f(-(float)half * 0.41524101186092029f);
    float ang = (float)t * alpha;
    float c = cosf(ang), s = sinf(ang);

    size_t off = ((size_t)b * T_ + t) * C_ + h * D_ + half;
    float xr = q[off], xi = q[off + 32];
    reinterpret_cast<uint32_t*>(q)[off]      = tf32r(xr * c - xi * s);
    reinterpret_cast<uint32_t*>(q)[off + 32] = tf32r(xr * s + xi * c);
    xr = k[off]; xi = k[off + 32];
    reinterpret_cast<uint32_t*>(k)[off]      = tf32r(xr * c - xi * s);
    reinterpret_cast<uint32_t*>(k)[off + 32] = tf32r(xr * s + xi * c);
}

// ---------------------------------------------------------------------------
// Tensor-core flash attention v2 (causal, tf32 mma, online softmax).
// CTA: 128 queries x one (b,h); 8 warps; warp owns 16 q rows.
// K/V pre-rounded tf32 in gmem -> cp.async double-buffered, raw.
// PV uses P as A-operand (k-slot permutation matches S C-layout), V row-major
// as B-operand (LDS.32 stride 68, conflict-free). y lands in C-layout:
// softmax corrections & 1/l apply in-register, direct float2 stores.
// ---------------------------------------------------------------------------
constexpr int LDQ = 72;                       // Q,K smem stride (floats)
constexpr int LDV = 68;                       // V smem stride (floats)
constexpr int QF = 128 * LDQ;                 // 9216
constexpr int KF = 64 * LDQ;                  // 4608 per buffer
constexpr int VF = 64 * LDV;                  // 4352 per buffer
constexpr int ATTN_SMEM3 = (QF + 2 * KF + 2 * VF) * 4;  // 108544 B

__global__ __launch_bounds__(256, 2) void attn_mma(
    const float* __restrict__ q, const float* __restrict__ k,
    const float* __restrict__ v, float* __restrict__ y)
{
    extern __shared__ __align__(16) float sma[];
    float* Qs = sma;                       // [128][72]
    float* Ksb = sma + QF;                 // [2][64][72]
    float* Vsb = sma + QF + 2 * KF;        // [2][64][68]
    const uint32_t sbase = smem_u32(sma);

    const int tid = threadIdx.x;
    const int lane = tid & 31, w = tid >> 5;
    const int r = lane >> 2, kc = lane & 3;
    const int qb = blockIdx.x, bh = blockIdx.y;
    const int b = bh >> 4, h = bh & 15;
    const int q0 = qb * 128;
    const size_t base = ((size_t)b * T_) * C_ + h * D_;

    // cp.async loader: K,V tile `it` (64 rows x 64 floats each) into buf it&1.
    // 64 rows x 16 float4-chunks = 1024 slots = 256 threads x 4 iters.
    const int crow = tid >> 4;             // 0..15 (+i*16 -> 0..63)
    const int cc4 = (tid & 15) * 4;        // 0..60: full 64-float row
    auto issue = [&](int it) {
        const int s0 = it * 64;
        const int buf = it & 1;
        const uint32_t kd = sbase + (uint32_t)(QF + buf * KF + crow * LDQ + cc4) * 4;
        const uint32_t vd = sbase + (uint32_t)(QF + 2 * KF + buf * VF + crow * LDV + cc4) * 4;
        const float* ks = &k[base + (size_t)(s0 + crow) * C_ + cc4];
        const float* vs = &v[base + (size_t)(s0 + crow) * C_ + cc4];
#pragma unroll
        for (int i = 0; i < 4; i++) {
            CP_ASYNC16(kd + (uint32_t)(i * 16 * LDQ) * 4, ks + (size_t)i * 16 * C_);
            CP_ASYNC16(vd + (uint32_t)(i * 16 * LDV) * 4, vs + (size_t)i * 16 * C_);
        }
        CP_COMMIT();
    };

    issue(0);

    // Load Q tile (pre-rounded tf32; x0.125 is exact on tf32)
#pragma unroll
    for (int it = 0; it < 8; it++) {
        int f = tid + it * 256;
        int row = f >> 4, d4 = f & 15;
        float4 t = *reinterpret_cast<const float4*>(
            &q[base + (size_t)(q0 + row) * C_ + d4 * 4]);
        t.x *= 0.125f; t.y *= 0.125f; t.z *= 0.125f; t.w *= 0.125f;
        *reinterpret_cast<float4*>(&Qs[row * LDQ + d4 * 4]) = t;
    }

    float sc[8][4];
    float yacc[8][4];
#pragma unroll
    for (int nt = 0; nt < 8; nt++)
#pragma unroll
        for (int j = 0; j < 4; j++) yacc[nt][j] = 0.f;
    float mA = -1e30f, mB = -1e30f, lA = 0.f, lB = 0.f;

    const int qrow0 = q0 + 16 * w;
    const int nit = 2 * qb + 2;
    for (int itk = 0; itk < nit; itk++) {
        const int s0 = itk * 64;
        CP_WAIT0();
        __syncthreads();
        if (itk + 1 < nit) issue(itk + 1);

        if (s0 <= qrow0 + 15) {
            const float* Kb = Ksb + (itk & 1) * KF;
            const float* Vb = Vsb + (itk & 1) * VF;

            // ---- S = Q K^T ----
#pragma unroll
            for (int nt = 0; nt < 8; nt++)
#pragma unroll
                for (int j = 0; j < 4; j++) sc[nt][j] = 0.f;

#pragma unroll
            for (int kk = 0; kk < 8; kk++) {
                uint2 a01 = *reinterpret_cast<const uint2*>(
                    &Qs[(16 * w + r) * LDQ + 8 * kk + 2 * kc]);
                uint2 a23 = *reinterpret_cast<const uint2*>(
                    &Qs[(16 * w + r + 8) * LDQ + 8 * kk + 2 * kc]);
#pragma unroll
                for (int nt = 0; nt < 8; nt++) {
                    uint2 bb = *reinterpret_cast<const uint2*>(
                        &Kb[(8 * nt + r) * LDQ + 8 * kk + 2 * kc]);
                    mma_u(sc[nt], a01.x, a23.x, a01.y, a23.y, bb.x, bb.y);
                }
            }

            // ---- causal mask (near diagonal only) ----
            if (s0 + 63 > qrow0) {
                const int qA = qrow0 + r, qB = qA + 8;
#pragma unroll
                for (int nt = 0; nt < 8; nt++) {
                    int sg = s0 + 8 * nt + 2 * kc;
                    if (sg > qA)     sc[nt][0] = -1e30f;
                    if (sg + 1 > qA) sc[nt][1] = -1e30f;
                    if (sg > qB)     sc[nt][2] = -1e30f;
                    if (sg + 1 > qB) sc[nt][3] = -1e30f;
                }
            }

            // ---- online softmax (rows A=qrow0+r, B=+8) ----
            float mxA = -1e30f, mxB = -1e30f;
#pragma unroll
            for (int nt = 0; nt < 8; nt++) {
                mxA = fmaxf(mxA, fmaxf(sc[nt][0], sc[nt][1]));
                mxB = fmaxf(mxB, fmaxf(sc[nt][2], sc[nt][3]));
            }
            mxA = fmaxf(mxA, __shfl_xor_sync(0xffffffffu, mxA, 1));
            mxA = fmaxf(mxA, __shfl_xor_sync(0xffffffffu, mxA, 2));
            mxB = fmaxf(mxB, __shfl_xor_sync(0xffffffffu, mxB, 1));
            mxB = fmaxf(mxB, __shfl_xor_sync(0xffffffffu, mxB, 2));
            float mnA = fmaxf(mA, mxA), mnB = fmaxf(mB, mxB);
            float cA = __expf(mA - mnA), cB = __expf(mB - mnB);
            mA = mnA; mB = mnB;
            float psA = 0.f, psB = 0.f;
#pragma unroll
            for (int nt = 0; nt < 8; nt++) {
                float p0 = __expf(sc[nt][0] - mnA);
                float p1 = __expf(sc[nt][1] - mnA);
                float p2 = __expf(sc[nt][2] - mnB);
                float p3 = __expf(sc[nt][3] - mnB);
                psA += p0 + p1; psB += p2 + p3;
                sc[nt][0] = p0; sc[nt][1] = p1; sc[nt][2] = p2; sc[nt][3] = p3;
            }
            psA += __shfl_xor_sync(0xffffffffu, psA, 1);
            psA += __shfl_xor_sync(0xffffffffu, psA, 2);
            psB += __shfl_xor_sync(0xffffffffu, psB, 1);
            psB += __shfl_xor_sync(0xffffffffu, psB, 2);
            lA = lA * cA + psA;
            lB = lB * cB + psB;

            // rescale y accumulators — rows owned by this thread, no shfl
#pragma unroll
            for (int nt = 0; nt < 8; nt++) {
                yacc[nt][0] *= cA; yacc[nt][1] *= cA;
                yacc[nt][2] *= cB; yacc[nt][3] *= cB;
            }

            // ---- P to tf32 ----
#pragma unroll
            for (int nt = 0; nt < 8; nt++)
#pragma unroll
                for (int j = 0; j < 4; j++)
                    sc[nt][j] = __uint_as_float(tf32r(sc[nt][j]));

            // ---- y += P V : P as A-operand (slot perm), V row-major as B ----
#pragma unroll
            for (int kk = 0; kk < 8; kk++) {
                uint32_t a0 = __float_as_uint(sc[kk][0]);
                uint32_t a1 = __float_as_uint(sc[kk][2]);
                uint32_t a2 = __float_as_uint(sc[kk][1]);
                uint32_t a3 = __float_as_uint(sc[kk][3]);
                const float* vr0 = &Vb[(8 * kk + 2 * kc) * LDV + r];
                const float* vr1 = vr0 + LDV;
#pragma unroll
                for (int nt = 0; nt < 8; nt++) {
                    uint32_t b0 = __float_as_uint(vr0[8 * nt]);
                    uint32_t b1 = __float_as_uint(vr1[8 * nt]);
                    mma_u(yacc[nt], a0, a1, a2, a3, b0, b1);
                }
            }
        }
    }

    // ---- epilogue: in-register normalize + rounded direct stores ----
    const float iA = 1.f / lA, iB = 1.f / lB;
    float* yA = &y[base + (size_t)(qrow0 + r) * C_];
    float* yB = &y[base + (size_t)(qrow0 + r + 8) * C_];
#pragma unroll
    for (int nt = 0; nt < 8; nt++) {
        const int cg = 8 * nt + 2 * kc;
        uint2 u0, u1;
        u0.x = tf32r(yacc[nt][0] * iA); u0.y = tf32r(yacc[nt][1] * iA);
        u1.x = tf32r(yacc[nt][2] * iB); u1.y = tf32r(yacc[nt][3] * iB);
        *reinterpret_cast<uint2*>(&yA[cg]) = u0;
        *reinterpret_cast<uint2*>(&yB[cg]) = u1;
    }
}

// ---------------------------------------------------------------------------
// Launch
// ---------------------------------------------------------------------------
extern "C" void kernel_launch(void* const* d_in, const int* in_sizes, int n_in,
                              void* d_out, int out_size)
{
    const float* x  = (const float*)d_in[0];
    const float* wq = (const float*)d_in[1];
    const float* bq = (const float*)d_in[2];
    const float* wk = (const float*)d_in[3];
    const float* bk = (const float*)d_in[4];
    const float* wv = (const float*)d_in[5];
    const float* bv = (const float*)d_in[6];
    const float* wp = (const float*)d_in[7];
    const float* bp = (const float*)d_in[8];
    float* out = (float*)d_out;

    float *qp, *kp, *vp, *yp, *xp, *wr;
    cudaGetSymbolAddress((void**)&qp, g_q);
    cudaGetSymbolAddress((void**)&kp, g_k);
    cudaGetSymbolAddress((void**)&vp, g_v);
    cudaGetSymbolAddress((void**)&yp, g_y);
    cudaGetSymbolAddress((void**)&xp, g_x);
    cudaGetSymbolAddress((void**)&wr, g_w);

    cudaFuncSetAttribute(gemm_mma,
                         cudaFuncAttributeMaxDynamicSharedMemorySize, GEMM_SMEM);
    cudaFuncSetAttribute(attn_mma,
                         cudaFuncAttributeMaxDynamicSharedMemorySize, ATTN_SMEM3);

    // Pre-round x and weights to tf32 (RNA) once.
    const int RBLK = (M_ * C_ / 4 + 4 * C_ * C_ / 4) / 256;  // 12288
    round_tf32<<<RBLK, 256>>>(x, wq, wk, wv, wp, xp, wr);

    // Fused QKV projection; v (z==2) stored tf32-rounded.
    dim3 qkv_grid(C_ / 128, M_ / 256, 3);   // (8, 32, 3)
    gemm_mma<<<qkv_grid, 256, GEMM_SMEM>>>(xp, wr, bq, bk, bv, qp, kp, vp, 2);

    rope_kernel<<<(B_ * T_ * H_ * 32) / 256, 256>>>(qp, kp);

    dim3 agrid(16, 64);                     // q-tiles x (b*h)
    attn_mma<<<agrid, 256, ATTN_SMEM3>>>(qp, kp, vp, yp);

    // Output projection (z = 0 only, no rounding).
    dim3 proj_grid(C_ / 128, M_ / 256, 1);  // (8, 32, 1)
    gemm_mma<<<proj_grid, 256, GEMM_SMEM>>>(yp, wr + 3 * (size_t)C_ * C_,
                                            bp, bp, bp, out, out, out, -1);
}